// round 1
// baseline (speedup 1.0000x reference)
#include <cuda_runtime.h>
#include <cstddef>

#define S    256
#define NSEQ 256
#define C    32
#define CZ   128
#define SC   8192     /* S*C */
#define KOUT 1024     /* C*C */
#define TK   8

// Scratch (allocation-free rule: __device__ globals)
__device__ float g_A[SC * NSEQ];                 //  8 MB: a'[(i*32+c)*256 + n], pre-scaled by 1/N
__device__ float g_B[SC * NSEQ];                 //  8 MB: b'[(j*32+d)*256 + n]
__device__ float g_O[(size_t)S * S * KOUT];      // 268 MB: O[(i*256+j)*1024 + c*32 + d]

// ---------------------------------------------------------------------------
// Kernel 1: LayerNorm + projection, writes A' (scaled by 1/N) and B'
// One block per s (256 threads = one per n).
// ---------------------------------------------------------------------------
__global__ __launch_bounds__(256) void prep_kernel(
    const float* __restrict__ m, const float* __restrict__ gamma,
    const float* __restrict__ beta, const float* __restrict__ Wab)
{
    __shared__ float sW[2 * C * C];
    __shared__ float sg[C], sb[C];
    const int tid = threadIdx.x;
    for (int i = tid; i < 2 * C * C; i += 256) sW[i] = Wab[i];
    if (tid < C) { sg[tid] = gamma[tid]; sb[tid] = beta[tid]; }
    __syncthreads();

    const int s = blockIdx.x;
    const int n = tid;
    const float* xp = m + ((size_t)s * NSEQ + n) * C;

    float x[C];
#pragma unroll
    for (int q = 0; q < C / 4; q++) {
        float4 v = reinterpret_cast<const float4*>(xp)[q];
        x[4*q+0] = v.x; x[4*q+1] = v.y; x[4*q+2] = v.z; x[4*q+3] = v.w;
    }
    float mu = 0.f;
#pragma unroll
    for (int c = 0; c < C; c++) mu += x[c];
    mu *= (1.f / C);
    float var = 0.f;
#pragma unroll
    for (int c = 0; c < C; c++) { float d = x[c] - mu; var += d * d; }
    var *= (1.f / C);
    const float rstd = rsqrtf(var + 1e-5f);
#pragma unroll
    for (int c = 0; c < C; c++) x[c] = (x[c] - mu) * rstd * sg[c] + sb[c];

#pragma unroll 4
    for (int d = 0; d < C; d++) {
        float acc = 0.f;
#pragma unroll
        for (int c = 0; c < C; c++) acc += x[c] * sW[d * C + c];
        g_A[(s * C + d) * NSEQ + n] = acc * (1.f / NSEQ);
    }
#pragma unroll 4
    for (int d = 0; d < C; d++) {
        float acc = 0.f;
#pragma unroll
        for (int c = 0; c < C; c++) acc += x[c] * sW[(C + d) * C + c];
        g_B[(s * C + d) * NSEQ + n] = acc;
    }
}

// ---------------------------------------------------------------------------
// Kernel 2: O = A' * B'^T   (M=N=8192, K=256), permuted epilogue into
// layout [(i*256+j)*1024 + c*32 + d].
// 128x128 CTA tile, 8x8 per thread (split 4+4 to bound smem conflicts).
// ---------------------------------------------------------------------------
__global__ __launch_bounds__(256) void gemm2_kernel()
{
    __shared__ float As[TK][128 + 4];
    __shared__ float Bs[TK][128 + 4];
    const int tid  = threadIdx.x;
    const int tx   = tid & 15;
    const int ty   = tid >> 4;
    const int row0 = blockIdx.y * 128;
    const int col0 = blockIdx.x * 128;
    const int lrow = tid >> 1;
    const int lk   = (tid & 1) * 4;

    const float* Ap = g_A + (size_t)(row0 + lrow) * NSEQ + lk;
    const float* Bp = g_B + (size_t)(col0 + lrow) * NSEQ + lk;

    float acc[8][8];
#pragma unroll
    for (int i = 0; i < 8; i++)
#pragma unroll
        for (int j = 0; j < 8; j++) acc[i][j] = 0.f;

    for (int k0 = 0; k0 < NSEQ; k0 += TK) {
        float4 av = *reinterpret_cast<const float4*>(Ap + k0);
        float4 bv = *reinterpret_cast<const float4*>(Bp + k0);
        As[lk+0][lrow] = av.x; As[lk+1][lrow] = av.y;
        As[lk+2][lrow] = av.z; As[lk+3][lrow] = av.w;
        Bs[lk+0][lrow] = bv.x; Bs[lk+1][lrow] = bv.y;
        Bs[lk+2][lrow] = bv.z; Bs[lk+3][lrow] = bv.w;
        __syncthreads();
#pragma unroll
        for (int k = 0; k < TK; k++) {
            float af[8], bf[8];
#pragma unroll
            for (int i = 0; i < 4; i++) {
                af[i]     = As[k][ty * 4 + i];
                af[4 + i] = As[k][64 + ty * 4 + i];
                bf[i]     = Bs[k][tx * 4 + i];
                bf[4 + i] = Bs[k][64 + tx * 4 + i];
            }
#pragma unroll
            for (int i = 0; i < 8; i++)
#pragma unroll
                for (int j = 0; j < 8; j++) acc[i][j] += af[i] * bf[j];
        }
        __syncthreads();
    }

#pragma unroll
    for (int i = 0; i < 8; i++) {
        const int R  = row0 + ((i < 4) ? (ty * 4 + i) : (64 + ty * 4 + (i - 4)));
        const int ii = R >> 5, cc = R & 31;
#pragma unroll
        for (int jh = 0; jh < 2; jh++) {
            const int Cc = col0 + ((jh == 0) ? (tx * 4) : (64 + tx * 4));
            const int jj = Cc >> 5, dd = Cc & 31;
            float4 v = make_float4(acc[i][jh*4+0], acc[i][jh*4+1],
                                   acc[i][jh*4+2], acc[i][jh*4+3]);
            *reinterpret_cast<float4*>(
                g_O + (size_t)(ii * S + jj) * KOUT + cc * C + dd) = v;
        }
    }
}

// ---------------------------------------------------------------------------
// Kernel 3: z = O * W_out^T + b_out   (M=65536, N=128, K=1024)
// Same tiling; single N tile (gridDim.x over M).
// ---------------------------------------------------------------------------
__global__ __launch_bounds__(256) void gemm3_kernel(
    const float* __restrict__ Wout, const float* __restrict__ bout,
    float* __restrict__ out)
{
    __shared__ float As[TK][128 + 4];
    __shared__ float Bs[TK][128 + 4];
    const int tid  = threadIdx.x;
    const int tx   = tid & 15;
    const int ty   = tid >> 4;
    const int row0 = blockIdx.x * 128;
    const int lrow = tid >> 1;
    const int lk   = (tid & 1) * 4;

    const float* Ap = g_O + (size_t)(row0 + lrow) * KOUT + lk;
    const float* Bp = Wout + (size_t)lrow * KOUT + lk;

    float acc[8][8];
#pragma unroll
    for (int i = 0; i < 8; i++)
#pragma unroll
        for (int j = 0; j < 8; j++) acc[i][j] = 0.f;

    for (int k0 = 0; k0 < KOUT; k0 += TK) {
        float4 av = *reinterpret_cast<const float4*>(Ap + k0);
        float4 bv = *reinterpret_cast<const float4*>(Bp + k0);
        As[lk+0][lrow] = av.x; As[lk+1][lrow] = av.y;
        As[lk+2][lrow] = av.z; As[lk+3][lrow] = av.w;
        Bs[lk+0][lrow] = bv.x; Bs[lk+1][lrow] = bv.y;
        Bs[lk+2][lrow] = bv.z; Bs[lk+3][lrow] = bv.w;
        __syncthreads();
#pragma unroll
        for (int k = 0; k < TK; k++) {
            float af[8], bf[8];
#pragma unroll
            for (int i = 0; i < 4; i++) {
                af[i]     = As[k][ty * 4 + i];
                af[4 + i] = As[k][64 + ty * 4 + i];
                bf[i]     = Bs[k][tx * 4 + i];
                bf[4 + i] = Bs[k][64 + tx * 4 + i];
            }
#pragma unroll
            for (int i = 0; i < 8; i++)
#pragma unroll
                for (int j = 0; j < 8; j++) acc[i][j] += af[i] * bf[j];
        }
        __syncthreads();
    }

#pragma unroll
    for (int i = 0; i < 8; i++) {
        const int R = row0 + ((i < 4) ? (ty * 4 + i) : (64 + ty * 4 + (i - 4)));
#pragma unroll
        for (int jh = 0; jh < 2; jh++) {
            const int Cc = (jh == 0) ? (tx * 4) : (64 + tx * 4);
            float4 v;
            v.x = acc[i][jh*4+0] + bout[Cc + 0];
            v.y = acc[i][jh*4+1] + bout[Cc + 1];
            v.z = acc[i][jh*4+2] + bout[Cc + 2];
            v.w = acc[i][jh*4+3] + bout[Cc + 3];
            *reinterpret_cast<float4*>(out + (size_t)R * CZ + Cc) = v;
        }
    }
}

// ---------------------------------------------------------------------------
extern "C" void kernel_launch(void* const* d_in, const int* in_sizes, int n_in,
                              void* d_out, int out_size)
{
    const float* m_si = (const float*)d_in[0];
    const float* gam  = (const float*)d_in[1];
    const float* bet  = (const float*)d_in[2];
    const float* Wab  = (const float*)d_in[3];
    const float* Wout = (const float*)d_in[4];
    const float* bout = (const float*)d_in[5];
    float* out = (float*)d_out;

    prep_kernel<<<S, 256>>>(m_si, gam, bet, Wab);
    gemm2_kernel<<<dim3(64, 64), 256>>>();
    gemm3_kernel<<<512, 256>>>(Wout, bout, out);
}

// round 4
// speedup vs baseline: 2.0090x; 2.0090x over previous
#include <cuda_runtime.h>
#include <cuda_bf16.h>
#include <cstdint>
#include <cstddef>

#define S_    256
#define NSEQ  256
#define C_    32
#define CZ    128
#define SC    8192      /* S*C */
#define KOUT  1024      /* C*C */

using bf16 = __nv_bfloat16;

// ----- scratch (__device__ globals; allocation-free rule) -------------------
__device__ __align__(16) bf16 g_Ahi[SC * NSEQ];               // 4 MB, K-major, scaled 1/N
__device__ __align__(16) bf16 g_Alo[SC * NSEQ];
__device__ __align__(16) bf16 g_Bhi[SC * NSEQ];
__device__ __align__(16) bf16 g_Blo[SC * NSEQ];
__device__ __align__(16) bf16 g_Ohi[(size_t)S_ * S_ * KOUT];  // 134 MB
__device__ __align__(16) bf16 g_Olo[(size_t)S_ * S_ * KOUT];  // 134 MB
__device__ __align__(16) bf16 g_Whi[CZ * KOUT];
__device__ __align__(16) bf16 g_Wlo[CZ * KOUT];

#define DEVINL __device__ __forceinline__

// ----- PTX helpers (all sm_80-era: safe for plain sm_100 target) ------------
DEVINL uint32_t smem_u32(const void* p) {
    uint32_t a;
    asm("{ .reg .u64 t; cvta.to.shared.u64 t, %1; cvt.u32.u64 %0, t; }"
        : "=r"(a) : "l"(p));
    return a;
}
DEVINL void cp16(uint32_t sdst, const void* gsrc) {
    asm volatile("cp.async.cg.shared.global [%0], [%1], 16;"
                 :: "r"(sdst), "l"(__cvta_generic_to_global(gsrc)) : "memory");
}
DEVINL void cp_commit() { asm volatile("cp.async.commit_group;" ::: "memory"); }
template <int N>
DEVINL void cp_wait() { asm volatile("cp.async.wait_group %0;" :: "n"(N) : "memory"); }

DEVINL void ldm4(uint32_t* r, uint32_t addr) {
    asm volatile("ldmatrix.sync.aligned.m8n8.x4.shared.b16 {%0,%1,%2,%3}, [%4];"
                 : "=r"(r[0]), "=r"(r[1]), "=r"(r[2]), "=r"(r[3]) : "r"(addr));
}
DEVINL void mma16816(float* c, const uint32_t* a, const uint32_t* b) {
    asm volatile(
        "mma.sync.aligned.m16n8k16.row.col.f32.bf16.bf16.f32 "
        "{%0,%1,%2,%3}, {%4,%5,%6,%7}, {%8,%9}, {%0,%1,%2,%3};"
        : "+f"(c[0]), "+f"(c[1]), "+f"(c[2]), "+f"(c[3])
        : "r"(a[0]), "r"(a[1]), "r"(a[2]), "r"(a[3]), "r"(b[0]), "r"(b[1]));
}

DEVINL void split_store(bf16* hi, bf16* lo, size_t idx, float v) {
    bf16 h = __float2bfloat16_rn(v);
    hi[idx] = h;
    lo[idx] = __float2bfloat16_rn(v - __bfloat162float(h));
}

// Smem geometry: 4 operand tiles per stage (Ahi, Alo, Bhi, Blo), each
// 128 rows x 32 bf16, padded to 80 B/row -> 10240 B per tile.
#define OPB       10240
#define STAGE_B   40960
#define SMEM_BYTES (2 * STAGE_B)   /* 80 KB */

// issue one stage of cp.async loads; 64 threads per operand array (o = tid>>6)
template <int RS>
DEVINL void issue_stage(const bf16* __restrict__ gb, uint32_t sdst_base, int k0, int tt) {
#pragma unroll
    for (int u = 0; u < 8; u++) {
        int q = u * 64 + tt;
        int r = q >> 2, ch = q & 3;
        cp16(sdst_base + (uint32_t)(r * 80 + ch * 16),
             gb + (size_t)r * RS + k0 + ch * 8);
    }
}

// one BK=32 stage of 3-pass split MMAs; warp tile 64x32
DEVINL void compute_stage(uint32_t st, int wm, int wn, int lane, float c[16][4]) {
    const uint32_t grp = lane >> 3, lr = lane & 7;
    const int arow = wm + (int)lr + (int)(grp & 1) * 8;
    const int brow = wn + (int)lr + (int)(grp >> 1) * 8;
#pragma unroll
    for (int kh = 0; kh < 2; kh++) {
        const uint32_t ag = kh * 2 + (grp >> 1);
        const uint32_t bg = kh * 2 + (grp & 1);
        uint32_t ah[4][4], al[4][4];
#pragma unroll
        for (int mt = 0; mt < 4; mt++) {
            uint32_t ad = st + (uint32_t)((arow + mt * 16) * 80) + ag * 16;
            ldm4(ah[mt], ad);
            ldm4(al[mt], ad + OPB);
        }
        uint32_t bh[8], bl[8];
#pragma unroll
        for (int bt = 0; bt < 2; bt++) {
            uint32_t bd = st + 2 * OPB + (uint32_t)((brow + bt * 16) * 80) + bg * 16;
            ldm4(&bh[bt * 4], bd);
            ldm4(&bl[bt * 4], bd + OPB);
        }
#pragma unroll
        for (int mt = 0; mt < 4; mt++)
#pragma unroll
            for (int nt = 0; nt < 4; nt++) {
                mma16816(c[mt * 4 + nt], ah[mt], &bh[nt * 2]);
                mma16816(c[mt * 4 + nt], ah[mt], &bl[nt * 2]);
                mma16816(c[mt * 4 + nt], al[mt], &bh[nt * 2]);
            }
    }
}

// ---------------------------------------------------------------------------
// Kernel 1: LayerNorm + projection -> bf16 hi/lo operands (a scaled by 1/N)
// ---------------------------------------------------------------------------
__global__ __launch_bounds__(256) void prep_kernel(
    const float* __restrict__ m, const float* __restrict__ gamma,
    const float* __restrict__ beta, const float* __restrict__ Wab)
{
    __shared__ float sW[2 * C_ * C_];
    __shared__ float sg[C_], sb[C_];
    const int tid = threadIdx.x;
    for (int i = tid; i < 2 * C_ * C_; i += 256) sW[i] = Wab[i];
    if (tid < C_) { sg[tid] = gamma[tid]; sb[tid] = beta[tid]; }
    __syncthreads();

    const int s = blockIdx.x;
    const int n = tid;
    const float* xp = m + ((size_t)s * NSEQ + n) * C_;

    float x[C_];
#pragma unroll
    for (int q = 0; q < C_ / 4; q++) {
        float4 v = reinterpret_cast<const float4*>(xp)[q];
        x[4*q+0] = v.x; x[4*q+1] = v.y; x[4*q+2] = v.z; x[4*q+3] = v.w;
    }
    float mu = 0.f;
#pragma unroll
    for (int c = 0; c < C_; c++) mu += x[c];
    mu *= (1.f / C_);
    float var = 0.f;
#pragma unroll
    for (int c = 0; c < C_; c++) { float d = x[c] - mu; var += d * d; }
    var *= (1.f / C_);
    const float rstd = rsqrtf(var + 1e-5f);
#pragma unroll
    for (int c = 0; c < C_; c++) x[c] = (x[c] - mu) * rstd * sg[c] + sb[c];

#pragma unroll 4
    for (int d = 0; d < C_; d++) {
        float acc = 0.f;
#pragma unroll
        for (int c = 0; c < C_; c++) acc += x[c] * sW[d * C_ + c];
        split_store(g_Ahi, g_Alo, (size_t)(s * C_ + d) * NSEQ + n, acc * (1.f / NSEQ));
    }
#pragma unroll 4
    for (int d = 0; d < C_; d++) {
        float acc = 0.f;
#pragma unroll
        for (int c = 0; c < C_; c++) acc += x[c] * sW[(C_ + d) * C_ + c];
        split_store(g_Bhi, g_Blo, (size_t)(s * C_ + d) * NSEQ + n, acc);
    }
}

__global__ __launch_bounds__(256) void wsplit_kernel(const float* __restrict__ W) {
    int i = blockIdx.x * 256 + threadIdx.x;
    split_store(g_Whi, g_Wlo, i, W[i]);
}

// ---------------------------------------------------------------------------
// Kernel 2: O = A' * B'^T  (M=N=8192, K=256) via mma.sync bf16 3-pass.
// Epilogue: permuted bf16 hi/lo write, layout [(i*256+j)*1024 + c*32 + d].
// ---------------------------------------------------------------------------
__global__ __launch_bounds__(256, 1) void gemm2_kernel()
{
    extern __shared__ __align__(128) char smem[];
    const uint32_t sb = smem_u32(smem);
    const int tid = threadIdx.x, lane = tid & 31, w = tid >> 5;
    const int wm = (w >> 2) * 64, wn = (w & 3) * 32;
    const int row0 = blockIdx.y * 128, col0 = blockIdx.x * 128;
    const int o = tid >> 6, tt = tid & 63;

    const bf16* gb;
    if      (o == 0) gb = g_Ahi + (size_t)row0 * NSEQ;
    else if (o == 1) gb = g_Alo + (size_t)row0 * NSEQ;
    else if (o == 2) gb = g_Bhi + (size_t)col0 * NSEQ;
    else             gb = g_Blo + (size_t)col0 * NSEQ;
    const uint32_t my_s = sb + (uint32_t)o * OPB;

    float c[16][4];
#pragma unroll
    for (int i = 0; i < 16; i++)
#pragma unroll
        for (int j = 0; j < 4; j++) c[i][j] = 0.f;

    const int NS = NSEQ / 32;  // 8
    issue_stage<NSEQ>(gb, my_s, 0, tt);
    cp_commit();
#pragma unroll 1
    for (int s = 0; s < NS; s++) {
        if (s + 1 < NS) {
            issue_stage<NSEQ>(gb, my_s + (uint32_t)((s + 1) & 1) * STAGE_B, (s + 1) * 32, tt);
            cp_commit();
            cp_wait<1>();
        } else {
            cp_wait<0>();
        }
        __syncthreads();
        compute_stage(sb + (uint32_t)(s & 1) * STAGE_B, wm, wn, lane, c);
        __syncthreads();
    }

    // permuted hi/lo epilogue
    const int R0 = row0 + wm + (lane >> 2);
#pragma unroll
    for (int mt = 0; mt < 4; mt++) {
#pragma unroll
        for (int h = 0; h < 2; h++) {
            const int R = R0 + mt * 16 + h * 8;
            const int i = R >> 5, cc = R & 31;
            const size_t rowbase = (size_t)i * (S_ * KOUT) + (size_t)cc * C_;
#pragma unroll
            for (int nt = 0; nt < 4; nt++) {
                const int Cc = col0 + wn + nt * 8 + (lane & 3) * 2;
                const int j = Cc >> 5, dd = Cc & 31;
                const size_t idx = rowbase + (size_t)j * KOUT + dd;
                float v0 = c[mt * 4 + nt][h * 2 + 0];
                float v1 = c[mt * 4 + nt][h * 2 + 1];
                bf16 h0 = __float2bfloat16_rn(v0), h1 = __float2bfloat16_rn(v1);
                __nv_bfloat162 hp; hp.x = h0; hp.y = h1;
                __nv_bfloat162 lp;
                lp.x = __float2bfloat16_rn(v0 - __bfloat162float(h0));
                lp.y = __float2bfloat16_rn(v1 - __bfloat162float(h1));
                *reinterpret_cast<__nv_bfloat162*>(g_Ohi + idx) = hp;
                *reinterpret_cast<__nv_bfloat162*>(g_Olo + idx) = lp;
            }
        }
    }
}

// ---------------------------------------------------------------------------
// Kernel 3: z = O * W_out^T + b  (M=65536, N=128, K=1024), same pipeline.
// ---------------------------------------------------------------------------
__global__ __launch_bounds__(256, 1) void gemm3_kernel(
    const float* __restrict__ bout, float* __restrict__ out)
{
    extern __shared__ __align__(128) char smem[];
    const uint32_t sb = smem_u32(smem);
    const int tid = threadIdx.x, lane = tid & 31, w = tid >> 5;
    const int wm = (w >> 2) * 64, wn = (w & 3) * 32;
    const int row0 = blockIdx.x * 128;
    const int o = tid >> 6, tt = tid & 63;

    const bf16* gb;
    if      (o == 0) gb = g_Ohi + (size_t)row0 * KOUT;
    else if (o == 1) gb = g_Olo + (size_t)row0 * KOUT;
    else if (o == 2) gb = g_Whi;
    else             gb = g_Wlo;
    const uint32_t my_s = sb + (uint32_t)o * OPB;

    float c[16][4];
#pragma unroll
    for (int i = 0; i < 16; i++)
#pragma unroll
        for (int j = 0; j < 4; j++) c[i][j] = 0.f;

    const int NS = KOUT / 32;  // 32
    issue_stage<KOUT>(gb, my_s, 0, tt);
    cp_commit();
#pragma unroll 1
    for (int s = 0; s < NS; s++) {
        if (s + 1 < NS) {
            issue_stage<KOUT>(gb, my_s + (uint32_t)((s + 1) & 1) * STAGE_B, (s + 1) * 32, tt);
            cp_commit();
            cp_wait<1>();
        } else {
            cp_wait<0>();
        }
        __syncthreads();
        compute_stage(sb + (uint32_t)(s & 1) * STAGE_B, wm, wn, lane, c);
        __syncthreads();
    }

    const int R0 = row0 + wm + (lane >> 2);
#pragma unroll
    for (int mt = 0; mt < 4; mt++) {
#pragma unroll
        for (int h = 0; h < 2; h++) {
            const int R = R0 + mt * 16 + h * 8;
#pragma unroll
            for (int nt = 0; nt < 4; nt++) {
                const int col = wn + nt * 8 + (lane & 3) * 2;
                float2 v;
                v.x = c[mt * 4 + nt][h * 2 + 0] + bout[col];
                v.y = c[mt * 4 + nt][h * 2 + 1] + bout[col + 1];
                *reinterpret_cast<float2*>(out + (size_t)R * CZ + col) = v;
            }
        }
    }
}

// ---------------------------------------------------------------------------
extern "C" void kernel_launch(void* const* d_in, const int* in_sizes, int n_in,
                              void* d_out, int out_size)
{
    const float* m_si = (const float*)d_in[0];
    const float* gam  = (const float*)d_in[1];
    const float* bet  = (const float*)d_in[2];
    const float* Wab  = (const float*)d_in[3];
    const float* Wout = (const float*)d_in[4];
    const float* bout = (const float*)d_in[5];
    float* out = (float*)d_out;

    cudaFuncSetAttribute(gemm2_kernel, cudaFuncAttributeMaxDynamicSharedMemorySize, SMEM_BYTES);
    cudaFuncSetAttribute(gemm3_kernel, cudaFuncAttributeMaxDynamicSharedMemorySize, SMEM_BYTES);

    prep_kernel<<<S_, 256>>>(m_si, gam, bet, Wab);
    wsplit_kernel<<<512, 256>>>(Wout);
    gemm2_kernel<<<dim3(64, 64), 256, SMEM_BYTES>>>();
    gemm3_kernel<<<512, 256, SMEM_BYTES>>>(bout, out);
}

// round 5
// speedup vs baseline: 2.2491x; 1.1195x over previous
#include <cuda_runtime.h>
#include <cuda_bf16.h>
#include <cstdint>
#include <cstddef>

#define S_    256
#define NSEQ  256
#define C_    32
#define CZ    128
#define SC    8192      /* S*C */
#define KOUT  1024      /* C*C */

using bf16 = __nv_bfloat16;

// ----- scratch (__device__ globals; allocation-free rule) -------------------
__device__ __align__(16) bf16 g_Ahi[SC * NSEQ];               // 4 MB, K-major, scaled 1/N
__device__ __align__(16) bf16 g_Alo[SC * NSEQ];
__device__ __align__(16) bf16 g_Bhi[SC * NSEQ];
__device__ __align__(16) bf16 g_Blo[SC * NSEQ];
__device__ __align__(16) bf16 g_Ohi[(size_t)S_ * S_ * KOUT];  // 134 MB
__device__ __align__(16) bf16 g_Olo[(size_t)S_ * S_ * KOUT];  // 134 MB
__device__ __align__(16) bf16 g_Whi[CZ * KOUT];
__device__ __align__(16) bf16 g_Wlo[CZ * KOUT];

#define DEVINL __device__ __forceinline__

// ----- PTX helpers (sm_80-era; required for plain sm_100 ptxas target) ------
DEVINL uint32_t smem_u32(const void* p) {
    uint32_t a;
    asm("{ .reg .u64 t; cvta.to.shared.u64 t, %1; cvt.u32.u64 %0, t; }"
        : "=r"(a) : "l"(p));
    return a;
}
DEVINL void cp16(uint32_t sdst, const void* gsrc) {
    asm volatile("cp.async.cg.shared.global [%0], [%1], 16;"
                 :: "r"(sdst), "l"(__cvta_generic_to_global(gsrc)) : "memory");
}
DEVINL void cp_commit() { asm volatile("cp.async.commit_group;" ::: "memory"); }
template <int N>
DEVINL void cp_wait() { asm volatile("cp.async.wait_group %0;" :: "n"(N) : "memory"); }

DEVINL void ldm4(uint32_t* r, uint32_t addr) {
    asm volatile("ldmatrix.sync.aligned.m8n8.x4.shared.b16 {%0,%1,%2,%3}, [%4];"
                 : "=r"(r[0]), "=r"(r[1]), "=r"(r[2]), "=r"(r[3]) : "r"(addr));
}
DEVINL void mma16816(float* c, const uint32_t* a, const uint32_t* b) {
    asm volatile(
        "mma.sync.aligned.m16n8k16.row.col.f32.bf16.bf16.f32 "
        "{%0,%1,%2,%3}, {%4,%5,%6,%7}, {%8,%9}, {%0,%1,%2,%3};"
        : "+f"(c[0]), "+f"(c[1]), "+f"(c[2]), "+f"(c[3])
        : "r"(a[0]), "r"(a[1]), "r"(a[2]), "r"(a[3]), "r"(b[0]), "r"(b[1]));
}

DEVINL void split_store(bf16* hi, bf16* lo, size_t idx, float v) {
    bf16 h = __float2bfloat16_rn(v);
    hi[idx] = h;
    lo[idx] = __float2bfloat16_rn(v - __bfloat162float(h));
}

// Smem per stage: Ahi(256x32) Alo Bhi(128x32) Blo, rows padded to 80B.
#define A_CB     20480             /* 256 rows * 80 B */
#define B_CB     10240             /* 128 rows * 80 B */
#define OFF_ALO  A_CB
#define OFF_BHI  (2 * A_CB)
#define OFF_BLO  (2 * A_CB + B_CB)
#define STAGE_B  (2 * A_CB + 2 * B_CB)   /* 61440 */
#define SMEM_BYTES (2 * STAGE_B)         /* 122880 */

// Load ROWS x 32 bf16 (64B rows) into 80B-pitch smem tile; 256 threads.
template <int RS, int ROWS>
DEVINL void stage_load(const bf16* __restrict__ g, uint32_t sdst, int k0, int tid) {
#pragma unroll
    for (int u = 0; u < ROWS * 4 / 256; u++) {
        int q = u * 256 + tid;
        int r = q >> 2, ch = q & 3;
        cp16(sdst + (uint32_t)(r * 80 + ch * 16),
             g + (size_t)r * RS + k0 + ch * 8);
    }
}

// One BK=32 stage of 3-pass split MMAs; warp tile 64x64 (4 m-tiles, 8 n-tiles).
DEVINL void compute_stage(uint32_t st, int wm, int wn, int lane, float c[4][8][4]) {
    const uint32_t grp = lane >> 3, lr = lane & 7;
    const int arow = wm + (int)lr + (int)(grp & 1) * 8;
    const int brow = wn + (int)lr + (int)(grp >> 1) * 8;
#pragma unroll
    for (int kh = 0; kh < 2; kh++) {
        const uint32_t ag = kh * 2 + (grp >> 1);
        const uint32_t bg = kh * 2 + (grp & 1);
        uint32_t ah[4][4], al[4][4];
#pragma unroll
        for (int mt = 0; mt < 4; mt++) {
            uint32_t ad = st + (uint32_t)((arow + mt * 16) * 80) + ag * 16;
            ldm4(ah[mt], ad);
            ldm4(al[mt], ad + OFF_ALO);
        }
#pragma unroll
        for (int bt = 0; bt < 4; bt++) {
            uint32_t bh[4], bl[4];
            uint32_t bd = st + OFF_BHI + (uint32_t)((brow + bt * 16) * 80) + bg * 16;
            ldm4(bh, bd);
            ldm4(bl, bd + B_CB);
#pragma unroll
            for (int mt = 0; mt < 4; mt++) {
                mma16816(c[mt][bt * 2],     ah[mt], bh);
                mma16816(c[mt][bt * 2],     ah[mt], bl);
                mma16816(c[mt][bt * 2],     al[mt], bh);
                mma16816(c[mt][bt * 2 + 1], ah[mt], bh + 2);
                mma16816(c[mt][bt * 2 + 1], ah[mt], bl + 2);
                mma16816(c[mt][bt * 2 + 1], al[mt], bh + 2);
            }
        }
    }
}

// ---------------------------------------------------------------------------
// Kernel 1: LayerNorm + projection -> bf16 hi/lo operands (a scaled by 1/N)
// ---------------------------------------------------------------------------
__global__ __launch_bounds__(256) void prep_kernel(
    const float* __restrict__ m, const float* __restrict__ gamma,
    const float* __restrict__ beta, const float* __restrict__ Wab)
{
    __shared__ float sW[2 * C_ * C_];
    __shared__ float sg[C_], sb[C_];
    const int tid = threadIdx.x;
    for (int i = tid; i < 2 * C_ * C_; i += 256) sW[i] = Wab[i];
    if (tid < C_) { sg[tid] = gamma[tid]; sb[tid] = beta[tid]; }
    __syncthreads();

    const int s = blockIdx.x;
    const int n = tid;
    const float* xp = m + ((size_t)s * NSEQ + n) * C_;

    float x[C_];
#pragma unroll
    for (int q = 0; q < C_ / 4; q++) {
        float4 v = reinterpret_cast<const float4*>(xp)[q];
        x[4*q+0] = v.x; x[4*q+1] = v.y; x[4*q+2] = v.z; x[4*q+3] = v.w;
    }
    float mu = 0.f;
#pragma unroll
    for (int c = 0; c < C_; c++) mu += x[c];
    mu *= (1.f / C_);
    float var = 0.f;
#pragma unroll
    for (int c = 0; c < C_; c++) { float d = x[c] - mu; var += d * d; }
    var *= (1.f / C_);
    const float rstd = rsqrtf(var + 1e-5f);
#pragma unroll
    for (int c = 0; c < C_; c++) x[c] = (x[c] - mu) * rstd * sg[c] + sb[c];

#pragma unroll 4
    for (int d = 0; d < C_; d++) {
        float acc = 0.f;
#pragma unroll
        for (int c = 0; c < C_; c++) acc += x[c] * sW[d * C_ + c];
        split_store(g_Ahi, g_Alo, (size_t)(s * C_ + d) * NSEQ + n, acc * (1.f / NSEQ));
    }
#pragma unroll 4
    for (int d = 0; d < C_; d++) {
        float acc = 0.f;
#pragma unroll
        for (int c = 0; c < C_; c++) acc += x[c] * sW[(C_ + d) * C_ + c];
        split_store(g_Bhi, g_Blo, (size_t)(s * C_ + d) * NSEQ + n, acc);
    }
}

__global__ __launch_bounds__(256) void wsplit_kernel(const float* __restrict__ W) {
    int i = blockIdx.x * 256 + threadIdx.x;
    split_store(g_Whi, g_Wlo, i, W[i]);
}

// ---------------------------------------------------------------------------
// Unified tensor-core GEMM: CTA tile 256x128, 8 warps of 64x64, 3-pass split.
// MODE 0: A'(8192xK) * B'(8192xK)^T, permuted hi/lo write to g_Ohi/g_Olo.
// MODE 1: O(65536xK) * W(128xK)^T + bias -> out fp32.
// ---------------------------------------------------------------------------
template <int KD, int MODE>
__global__ __launch_bounds__(256, 1) void gemm_kernel(
    const float* __restrict__ bout, float* __restrict__ out)
{
    extern __shared__ __align__(128) char smem[];
    const uint32_t sbase = smem_u32(smem);
    const int tid = threadIdx.x, lane = tid & 31, w = tid >> 5;
    const int wm = (w >> 1) * 64, wn = (w & 1) * 64;
    const int row0 = blockIdx.y * 256;
    const int col0 = blockIdx.x * 128;

    const bf16 *pAh, *pAl, *pBh, *pBl;
    if (MODE == 0) {
        pAh = g_Ahi + (size_t)row0 * KD;  pAl = g_Alo + (size_t)row0 * KD;
        pBh = g_Bhi + (size_t)col0 * KD;  pBl = g_Blo + (size_t)col0 * KD;
    } else {
        pAh = g_Ohi + (size_t)row0 * KD;  pAl = g_Olo + (size_t)row0 * KD;
        pBh = g_Whi;                      pBl = g_Wlo;
    }

    float bias[16];
    if (MODE == 1) {
#pragma unroll
        for (int nt = 0; nt < 8; nt++) {
            const int col = wn + nt * 8 + (lane & 3) * 2;
            bias[nt * 2]     = bout[col];
            bias[nt * 2 + 1] = bout[col + 1];
        }
    }

    float c[4][8][4];
#pragma unroll
    for (int a = 0; a < 4; a++)
#pragma unroll
        for (int b = 0; b < 8; b++)
#pragma unroll
            for (int d = 0; d < 4; d++) c[a][b][d] = 0.f;

    const int NS = KD / 32;
    stage_load<KD, 256>(pAh, sbase,           0, tid);
    stage_load<KD, 256>(pAl, sbase + OFF_ALO, 0, tid);
    stage_load<KD, 128>(pBh, sbase + OFF_BHI, 0, tid);
    stage_load<KD, 128>(pBl, sbase + OFF_BLO, 0, tid);
    cp_commit();
#pragma unroll 1
    for (int s = 0; s < NS; s++) {
        if (s + 1 < NS) {
            const uint32_t nb = sbase + (uint32_t)((s + 1) & 1) * STAGE_B;
            const int k0 = (s + 1) * 32;
            stage_load<KD, 256>(pAh, nb,           k0, tid);
            stage_load<KD, 256>(pAl, nb + OFF_ALO, k0, tid);
            stage_load<KD, 128>(pBh, nb + OFF_BHI, k0, tid);
            stage_load<KD, 128>(pBl, nb + OFF_BLO, k0, tid);
            cp_commit();
            cp_wait<1>();
        } else {
            cp_wait<0>();
        }
        __syncthreads();
        compute_stage(sbase + (uint32_t)(s & 1) * STAGE_B, wm, wn, lane, c);
        __syncthreads();
    }

    const int R0 = row0 + wm + (lane >> 2);
    if (MODE == 0) {
#pragma unroll
        for (int mt = 0; mt < 4; mt++) {
#pragma unroll
            for (int h = 0; h < 2; h++) {
                const int R = R0 + mt * 16 + h * 8;
                const int i = R >> 5, cc = R & 31;
                const size_t rowbase = (size_t)i * (S_ * KOUT) + (size_t)cc * C_;
#pragma unroll
                for (int nt = 0; nt < 8; nt++) {
                    const int Cc = col0 + wn + nt * 8 + (lane & 3) * 2;
                    const int j = Cc >> 5, dd = Cc & 31;
                    const size_t idx = rowbase + (size_t)j * KOUT + dd;
                    float v0 = c[mt][nt][h * 2 + 0];
                    float v1 = c[mt][nt][h * 2 + 1];
                    bf16 h0 = __float2bfloat16_rn(v0), h1 = __float2bfloat16_rn(v1);
                    __nv_bfloat162 hp; hp.x = h0; hp.y = h1;
                    __nv_bfloat162 lp;
                    lp.x = __float2bfloat16_rn(v0 - __bfloat162float(h0));
                    lp.y = __float2bfloat16_rn(v1 - __bfloat162float(h1));
                    *reinterpret_cast<__nv_bfloat162*>(g_Ohi + idx) = hp;
                    *reinterpret_cast<__nv_bfloat162*>(g_Olo + idx) = lp;
                }
            }
        }
    } else {
#pragma unroll
        for (int mt = 0; mt < 4; mt++) {
#pragma unroll
            for (int h = 0; h < 2; h++) {
                const int R = R0 + mt * 16 + h * 8;
#pragma unroll
                for (int nt = 0; nt < 8; nt++) {
                    const int col = wn + nt * 8 + (lane & 3) * 2;
                    float2 v;
                    v.x = c[mt][nt][h * 2 + 0] + bias[nt * 2];
                    v.y = c[mt][nt][h * 2 + 1] + bias[nt * 2 + 1];
                    *reinterpret_cast<float2*>(out + (size_t)R * CZ + col) = v;
                }
            }
        }
    }
}

// ---------------------------------------------------------------------------
extern "C" void kernel_launch(void* const* d_in, const int* in_sizes, int n_in,
                              void* d_out, int out_size)
{
    const float* m_si = (const float*)d_in[0];
    const float* gam  = (const float*)d_in[1];
    const float* bet  = (const float*)d_in[2];
    const float* Wab  = (const float*)d_in[3];
    const float* Wout = (const float*)d_in[4];
    const float* bout = (const float*)d_in[5];
    float* out = (float*)d_out;

    cudaFuncSetAttribute(gemm_kernel<NSEQ, 0>,
                         cudaFuncAttributeMaxDynamicSharedMemorySize, SMEM_BYTES);
    cudaFuncSetAttribute(gemm_kernel<KOUT, 1>,
                         cudaFuncAttributeMaxDynamicSharedMemorySize, SMEM_BYTES);

    prep_kernel<<<S_, 256>>>(m_si, gam, bet, Wab);
    wsplit_kernel<<<512, 256>>>(Wout);
    gemm_kernel<NSEQ, 0><<<dim3(64, 32), 256, SMEM_BYTES>>>(nullptr, nullptr);
    gemm_kernel<KOUT, 1><<<dim3(1, 256), 256, SMEM_BYTES>>>(bout, out);
}

// round 7
// speedup vs baseline: 2.5764x; 1.1455x over previous
#include <cuda_runtime.h>
#include <cuda_bf16.h>
#include <cstdint>
#include <cstddef>

#define S_    256
#define NSEQ  256
#define C_    32
#define CZ    128
#define SC    8192      /* S*C */
#define KOUT  1024      /* C*C */

using bf16 = __nv_bfloat16;

// ----- scratch (__device__ globals; allocation-free rule) -------------------
__device__ __align__(16) bf16 g_Ahi[SC * NSEQ];               // 4 MB, K-major, scaled 1/N
__device__ __align__(16) bf16 g_Alo[SC * NSEQ];
__device__ __align__(16) bf16 g_Bhi[SC * NSEQ];
__device__ __align__(16) bf16 g_Blo[SC * NSEQ];
__device__ __align__(16) bf16 g_Ohi[(size_t)S_ * S_ * KOUT];  // 134 MB
__device__ __align__(16) bf16 g_Olo[(size_t)S_ * S_ * KOUT];  // 134 MB
__device__ __align__(16) bf16 g_Whi[CZ * KOUT];
__device__ __align__(16) bf16 g_Wlo[CZ * KOUT];

#define DEVINL __device__ __forceinline__

// ----- PTX helpers (sm_80-era; required for plain sm_100 ptxas target) ------
DEVINL uint32_t smem_u32(const void* p) {
    uint32_t a;
    asm("{ .reg .u64 t; cvta.to.shared.u64 t, %1; cvt.u32.u64 %0, t; }"
        : "=r"(a) : "l"(p));
    return a;
}
DEVINL void cp16(uint32_t sdst, const void* gsrc) {
    asm volatile("cp.async.cg.shared.global [%0], [%1], 16;"
                 :: "r"(sdst), "l"(__cvta_generic_to_global(gsrc)) : "memory");
}
DEVINL void cp_commit() { asm volatile("cp.async.commit_group;" ::: "memory"); }
template <int N>
DEVINL void cp_wait() { asm volatile("cp.async.wait_group %0;" :: "n"(N) : "memory"); }

DEVINL void ldm4(uint32_t* r, uint32_t addr) {
    asm volatile("ldmatrix.sync.aligned.m8n8.x4.shared.b16 {%0,%1,%2,%3}, [%4];"
                 : "=r"(r[0]), "=r"(r[1]), "=r"(r[2]), "=r"(r[3]) : "r"(addr));
}
DEVINL void mma16816(float* c, const uint32_t* a, const uint32_t* b) {
    asm volatile(
        "mma.sync.aligned.m16n8k16.row.col.f32.bf16.bf16.f32 "
        "{%0,%1,%2,%3}, {%4,%5,%6,%7}, {%8,%9}, {%0,%1,%2,%3};"
        : "+f"(c[0]), "+f"(c[1]), "+f"(c[2]), "+f"(c[3])
        : "r"(a[0]), "r"(a[1]), "r"(a[2]), "r"(a[3]), "r"(b[0]), "r"(b[1]));
}

DEVINL void split_store(bf16* hi, bf16* lo, size_t idx, float v) {
    bf16 h = __float2bfloat16_rn(v);
    hi[idx] = h;
    lo[idx] = __float2bfloat16_rn(v - __bfloat162float(h));
}

// Smem per stage: Ahi(128x32) Alo Bhi(128x32) Blo, rows padded to 80B.
#define T_CB     10240             /* 128 rows * 80 B */
#define OFF_ALO  T_CB
#define OFF_BHI  (2 * T_CB)
#define OFF_BLO  (3 * T_CB)
#define STAGE_B  (4 * T_CB)        /* 40960 */
#define SMEM_BYTES (2 * STAGE_B)   /* 81920 per CTA; 2 CTAs/SM = 160 KB */

// Load 128 rows x 32 bf16 (64B rows) into 80B-pitch smem tile; 128 threads.
template <int RS>
DEVINL void stage_load(const bf16* __restrict__ g, uint32_t sdst, int k0, int tid) {
#pragma unroll
    for (int u = 0; u < 4; u++) {
        int q = u * 128 + tid;
        int r = q >> 2, ch = q & 3;
        cp16(sdst + (uint32_t)(r * 80 + ch * 16),
             g + (size_t)r * RS + k0 + ch * 8);
    }
}

// One BK=32 stage of 3-pass split MMAs; warp tile 64x64 (4 m-tiles, 8 n-tiles).
DEVINL void compute_stage(uint32_t st, int wm, int wn, int lane, float c[4][8][4]) {
    const uint32_t grp = lane >> 3, lr = lane & 7;
    const int arow = wm + (int)lr + (int)(grp & 1) * 8;
    const int brow = wn + (int)lr + (int)(grp >> 1) * 8;
#pragma unroll
    for (int kh = 0; kh < 2; kh++) {
        const uint32_t ag = kh * 2 + (grp >> 1);
        const uint32_t bg = kh * 2 + (grp & 1);
        uint32_t ah[4][4], al[4][4];
#pragma unroll
        for (int mt = 0; mt < 4; mt++) {
            uint32_t ad = st + (uint32_t)((arow + mt * 16) * 80) + ag * 16;
            ldm4(ah[mt], ad);
            ldm4(al[mt], ad + OFF_ALO);
        }
#pragma unroll
        for (int bt = 0; bt < 4; bt++) {
            uint32_t bh[4], bl[4];
            uint32_t bd = st + OFF_BHI + (uint32_t)((brow + bt * 16) * 80) + bg * 16;
            ldm4(bh, bd);
            ldm4(bl, bd + T_CB);
#pragma unroll
            for (int mt = 0; mt < 4; mt++) {
                mma16816(c[mt][bt * 2],     ah[mt], bh);
                mma16816(c[mt][bt * 2],     ah[mt], bl);
                mma16816(c[mt][bt * 2],     al[mt], bh);
                mma16816(c[mt][bt * 2 + 1], ah[mt], bh + 2);
                mma16816(c[mt][bt * 2 + 1], ah[mt], bl + 2);
                mma16816(c[mt][bt * 2 + 1], al[mt], bh + 2);
            }
        }
    }
}

// ---------------------------------------------------------------------------
// Kernel 1: LayerNorm + projection -> bf16 hi/lo operands (a scaled by 1/N)
// ---------------------------------------------------------------------------
__global__ __launch_bounds__(256) void prep_kernel(
    const float* __restrict__ m, const float* __restrict__ gamma,
    const float* __restrict__ beta, const float* __restrict__ Wab)
{
    __shared__ float sW[2 * C_ * C_];
    __shared__ float sg[C_], sb[C_];
    const int tid = threadIdx.x;
    for (int i = tid; i < 2 * C_ * C_; i += 256) sW[i] = Wab[i];
    if (tid < C_) { sg[tid] = gamma[tid]; sb[tid] = beta[tid]; }
    __syncthreads();

    const int s = blockIdx.x;
    const int n = tid;
    const float* xp = m + ((size_t)s * NSEQ + n) * C_;

    float x[C_];
#pragma unroll
    for (int q = 0; q < C_ / 4; q++) {
        float4 v = reinterpret_cast<const float4*>(xp)[q];
        x[4*q+0] = v.x; x[4*q+1] = v.y; x[4*q+2] = v.z; x[4*q+3] = v.w;
    }
    float mu = 0.f;
#pragma unroll
    for (int c = 0; c < C_; c++) mu += x[c];
    mu *= (1.f / C_);
    float var = 0.f;
#pragma unroll
    for (int c = 0; c < C_; c++) { float d = x[c] - mu; var += d * d; }
    var *= (1.f / C_);
    const float rstd = rsqrtf(var + 1e-5f);
#pragma unroll
    for (int c = 0; c < C_; c++) x[c] = (x[c] - mu) * rstd * sg[c] + sb[c];

#pragma unroll 4
    for (int d = 0; d < C_; d++) {
        float acc = 0.f;
#pragma unroll
        for (int c = 0; c < C_; c++) acc += x[c] * sW[d * C_ + c];
        split_store(g_Ahi, g_Alo, (size_t)(s * C_ + d) * NSEQ + n, acc * (1.f / NSEQ));
    }
#pragma unroll 4
    for (int d = 0; d < C_; d++) {
        float acc = 0.f;
#pragma unroll
        for (int c = 0; c < C_; c++) acc += x[c] * sW[(C_ + d) * C_ + c];
        split_store(g_Bhi, g_Blo, (size_t)(s * C_ + d) * NSEQ + n, acc);
    }
}

__global__ __launch_bounds__(256) void wsplit_kernel(const float* __restrict__ W) {
    int i = blockIdx.x * 256 + threadIdx.x;
    split_store(g_Whi, g_Wlo, i, W[i]);
}

// ---------------------------------------------------------------------------
// Unified tensor-core GEMM: CTA tile 128x128, 4 warps of 64x64, 3-pass split.
// 2 CTAs/SM so one CTA's barrier/DRAM stalls overlap the other's MMAs.
// MODE 0: A'(8192xK) * B'(8192xK)^T, permuted hi/lo write to g_Ohi/g_Olo.
// MODE 1: O(65536xK) * W(128xK)^T + bias -> out fp32.
// ---------------------------------------------------------------------------
template <int KD, int MODE>
__global__ __launch_bounds__(128, 2) void gemm_kernel(
    const float* __restrict__ bout, float* __restrict__ out)
{
    extern __shared__ __align__(128) char smem[];
    const uint32_t sbase = smem_u32(smem);
    const int tid = threadIdx.x, lane = tid & 31, w = tid >> 5;
    const int wm = (w >> 1) * 64, wn = (w & 1) * 64;
    const int row0 = blockIdx.y * 128;
    const int col0 = blockIdx.x * 128;

    const bf16 *pAh, *pAl, *pBh, *pBl;
    if (MODE == 0) {
        pAh = g_Ahi + (size_t)row0 * KD;  pAl = g_Alo + (size_t)row0 * KD;
        pBh = g_Bhi + (size_t)col0 * KD;  pBl = g_Blo + (size_t)col0 * KD;
    } else {
        pAh = g_Ohi + (size_t)row0 * KD;  pAl = g_Olo + (size_t)row0 * KD;
        pBh = g_Whi;                      pBl = g_Wlo;
    }

    float bias[16];
    if (MODE == 1) {
#pragma unroll
        for (int nt = 0; nt < 8; nt++) {
            const int col = wn + nt * 8 + (lane & 3) * 2;
            bias[nt * 2]     = bout[col];
            bias[nt * 2 + 1] = bout[col + 1];
        }
    }

    float c[4][8][4];
#pragma unroll
    for (int a = 0; a < 4; a++)
#pragma unroll
        for (int b = 0; b < 8; b++)
#pragma unroll
            for (int d = 0; d < 4; d++) c[a][b][d] = 0.f;

    const int NS = KD / 32;
    stage_load<KD>(pAh, sbase,           0, tid);
    stage_load<KD>(pAl, sbase + OFF_ALO, 0, tid);
    stage_load<KD>(pBh, sbase + OFF_BHI, 0, tid);
    stage_load<KD>(pBl, sbase + OFF_BLO, 0, tid);
    cp_commit();
#pragma unroll 1
    for (int s = 0; s < NS; s++) {
        if (s + 1 < NS) {
            const uint32_t nb = sbase + (uint32_t)((s + 1) & 1) * STAGE_B;
            const int k0 = (s + 1) * 32;
            stage_load<KD>(pAh, nb,           k0, tid);
            stage_load<KD>(pAl, nb + OFF_ALO, k0, tid);
            stage_load<KD>(pBh, nb + OFF_BHI, k0, tid);
            stage_load<KD>(pBl, nb + OFF_BLO, k0, tid);
            cp_commit();
            cp_wait<1>();
        } else {
            cp_wait<0>();
        }
        __syncthreads();
        compute_stage(sbase + (uint32_t)(s & 1) * STAGE_B, wm, wn, lane, c);
        __syncthreads();
    }

    const int R0 = row0 + wm + (lane >> 2);
    if (MODE == 0) {
#pragma unroll
        for (int mt = 0; mt < 4; mt++) {
#pragma unroll
            for (int h = 0; h < 2; h++) {
                const int R = R0 + mt * 16 + h * 8;
                const int i = R >> 5, cc = R & 31;
                const size_t rowbase = (size_t)i * (S_ * KOUT) + (size_t)cc * C_;
#pragma unroll
                for (int nt = 0; nt < 8; nt++) {
                    const int Cc = col0 + wn + nt * 8 + (lane & 3) * 2;
                    const int j = Cc >> 5, dd = Cc & 31;
                    const size_t idx = rowbase + (size_t)j * KOUT + dd;
                    float v0 = c[mt][nt][h * 2 + 0];
                    float v1 = c[mt][nt][h * 2 + 1];
                    bf16 h0 = __float2bfloat16_rn(v0), h1 = __float2bfloat16_rn(v1);
                    __nv_bfloat162 hp; hp.x = h0; hp.y = h1;
                    __nv_bfloat162 lp;
                    lp.x = __float2bfloat16_rn(v0 - __bfloat162float(h0));
                    lp.y = __float2bfloat16_rn(v1 - __bfloat162float(h1));
                    *reinterpret_cast<__nv_bfloat162*>(g_Ohi + idx) = hp;
                    *reinterpret_cast<__nv_bfloat162*>(g_Olo + idx) = lp;
                }
            }
        }
    } else {
#pragma unroll
        for (int mt = 0; mt < 4; mt++) {
#pragma unroll
            for (int h = 0; h < 2; h++) {
                const int R = R0 + mt * 16 + h * 8;
#pragma unroll
                for (int nt = 0; nt < 8; nt++) {
                    const int col = wn + nt * 8 + (lane & 3) * 2;
                    float2 v;
                    v.x = c[mt][nt][h * 2 + 0] + bias[nt * 2];
                    v.y = c[mt][nt][h * 2 + 1] + bias[nt * 2 + 1];
                    *reinterpret_cast<float2*>(out + (size_t)R * CZ + col) = v;
                }
            }
        }
    }
}

// ---------------------------------------------------------------------------
extern "C" void kernel_launch(void* const* d_in, const int* in_sizes, int n_in,
                              void* d_out, int out_size)
{
    const float* m_si = (const float*)d_in[0];
    const float* gam  = (const float*)d_in[1];
    const float* bet  = (const float*)d_in[2];
    const float* Wab  = (const float*)d_in[3];
    const float* Wout = (const float*)d_in[4];
    const float* bout = (const float*)d_in[5];
    float* out = (float*)d_out;

    cudaFuncSetAttribute(gemm_kernel<NSEQ, 0>,
                         cudaFuncAttributeMaxDynamicSharedMemorySize, SMEM_BYTES);
    cudaFuncSetAttribute(gemm_kernel<KOUT, 1>,
                         cudaFuncAttributeMaxDynamicSharedMemorySize, SMEM_BYTES);

    prep_kernel<<<S_, 256>>>(m_si, gam, bet, Wab);
    wsplit_kernel<<<512, 256>>>(Wout);
    gemm_kernel<NSEQ, 0><<<dim3(64, 64), 128, SMEM_BYTES>>>(nullptr, nullptr);
    gemm_kernel<KOUT, 1><<<dim3(1, 512), 128, SMEM_BYTES>>>(bout, out);
}

// round 9
// speedup vs baseline: 2.9836x; 1.1581x over previous
#include <cuda_runtime.h>
#include <cuda_bf16.h>
#include <cstdint>
#include <cstddef>

#define S_    256
#define NSEQ  256
#define C_    32
#define CZ    128
#define SC    8192      /* S*C */
#define KOUT  1024      /* C*C */

using bf16 = __nv_bfloat16;

// ----- scratch (__device__ globals; allocation-free rule) -------------------
__device__ __align__(16) bf16 g_Ahi[SC * NSEQ];               // 4 MB, K-major, scaled 1/N
__device__ __align__(16) bf16 g_Alo[SC * NSEQ];
__device__ __align__(16) bf16 g_Bhi[SC * NSEQ];
__device__ __align__(16) bf16 g_Blo[SC * NSEQ];
__device__ __align__(16) bf16 g_Ohi[(size_t)S_ * S_ * KOUT];  // 134 MB
__device__ __align__(16) bf16 g_Olo[(size_t)S_ * S_ * KOUT];  // 134 MB
__device__ __align__(16) bf16 g_Whi[CZ * KOUT];
__device__ __align__(16) bf16 g_Wlo[CZ * KOUT];

#define DEVINL __device__ __forceinline__

// ----- PTX helpers (sm_80-era; required for plain sm_100 ptxas target) ------
DEVINL uint32_t smem_u32(const void* p) {
    uint32_t a;
    asm("{ .reg .u64 t; cvta.to.shared.u64 t, %1; cvt.u32.u64 %0, t; }"
        : "=r"(a) : "l"(p));
    return a;
}
DEVINL void cp16(uint32_t sdst, const void* gsrc) {
    asm volatile("cp.async.cg.shared.global [%0], [%1], 16;"
                 :: "r"(sdst), "l"(__cvta_generic_to_global(gsrc)) : "memory");
}
DEVINL void cp_commit() { asm volatile("cp.async.commit_group;" ::: "memory"); }
template <int N>
DEVINL void cp_wait() { asm volatile("cp.async.wait_group %0;" :: "n"(N) : "memory"); }

DEVINL void ldm4(uint32_t* r, uint32_t addr) {
    asm volatile("ldmatrix.sync.aligned.m8n8.x4.shared.b16 {%0,%1,%2,%3}, [%4];"
                 : "=r"(r[0]), "=r"(r[1]), "=r"(r[2]), "=r"(r[3]) : "r"(addr));
}
DEVINL void mma16816(float* c, const uint32_t* a, const uint32_t* b) {
    asm volatile(
        "mma.sync.aligned.m16n8k16.row.col.f32.bf16.bf16.f32 "
        "{%0,%1,%2,%3}, {%4,%5,%6,%7}, {%8,%9}, {%0,%1,%2,%3};"
        : "+f"(c[0]), "+f"(c[1]), "+f"(c[2]), "+f"(c[3])
        : "r"(a[0]), "r"(a[1]), "r"(a[2]), "r"(a[3]), "r"(b[0]), "r"(b[1]));
}

DEVINL void split_store(bf16* hi, bf16* lo, size_t idx, float v) {
    bf16 h = __float2bfloat16_rn(v);
    hi[idx] = h;
    lo[idx] = __float2bfloat16_rn(v - __bfloat162float(h));
}

// XOR-swizzled smem tile: 128 rows x 64 B (32 bf16), no padding.
// chunk ch (16B units) at row r lands at column (ch ^ ((r>>1)&3)).
// -> conflict-free ldmatrix (8 distinct 16B bank-groups per 8-row read)
//    and perfectly balanced 16B stores.
DEVINL uint32_t swz(int r, int ch) {
    return (uint32_t)(r * 64 + ((ch ^ ((r >> 1) & 3)) << 4));
}

#define T_CB     8192              /* 128 rows * 64 B */
#define OFF_ALO  T_CB
#define OFF_BHI  (2 * T_CB)
#define OFF_BLO  (3 * T_CB)
#define STAGE_B  (4 * T_CB)        /* 32768 */
#define NSTAGE   3
#define SMEM_BYTES (NSTAGE * STAGE_B)   /* 98304/CTA; 2 CTAs/SM = 192 KB */

// Load 128 rows x 32 bf16 into swizzled smem tile; 128 threads, 4 cp16 each.
template <int RS>
DEVINL void stage_load(const bf16* __restrict__ g, uint32_t sdst, int k0, int tid) {
#pragma unroll
    for (int u = 0; u < 4; u++) {
        int q = u * 128 + tid;
        int r = q >> 2, ch = q & 3;
        cp16(sdst + swz(r, ch), g + (size_t)r * RS + k0 + ch * 8);
    }
}

// One BK=32 stage of 3-pass split MMAs; warp tile 64x64 (4 m-tiles, 8 n-tiles).
DEVINL void compute_stage(uint32_t st, int wm, int wn, int lane, float c[4][8][4]) {
    const int grp = lane >> 3, lr = lane & 7;
    const int arow = wm + lr + (grp & 1) * 8;
    const int brow = wn + lr + (grp >> 1) * 8;
#pragma unroll
    for (int kh = 0; kh < 2; kh++) {
        const int ag = kh * 2 + (grp >> 1);
        const int bg = kh * 2 + (grp & 1);
        uint32_t ah[4][4], al[4][4];
#pragma unroll
        for (int mt = 0; mt < 4; mt++) {
            const int ra = arow + mt * 16;
            uint32_t ad = st + swz(ra, ag);
            ldm4(ah[mt], ad);
            ldm4(al[mt], ad + OFF_ALO);
        }
#pragma unroll
        for (int bt = 0; bt < 4; bt++) {
            uint32_t bh[4], bl[4];
            const int rb = brow + bt * 16;
            uint32_t bd = st + OFF_BHI + swz(rb, bg);
            ldm4(bh, bd);
            ldm4(bl, bd + T_CB);
#pragma unroll
            for (int mt = 0; mt < 4; mt++) {
                mma16816(c[mt][bt * 2],     ah[mt], bh);
                mma16816(c[mt][bt * 2],     ah[mt], bl);
                mma16816(c[mt][bt * 2],     al[mt], bh);
                mma16816(c[mt][bt * 2 + 1], ah[mt], bh + 2);
                mma16816(c[mt][bt * 2 + 1], ah[mt], bl + 2);
                mma16816(c[mt][bt * 2 + 1], al[mt], bh + 2);
            }
        }
    }
}

// ---------------------------------------------------------------------------
// Kernel 1: LayerNorm + projection -> bf16 hi/lo operands (a scaled by 1/N)
// ---------------------------------------------------------------------------
__global__ __launch_bounds__(256) void prep_kernel(
    const float* __restrict__ m, const float* __restrict__ gamma,
    const float* __restrict__ beta, const float* __restrict__ Wab)
{
    __shared__ float sW[2 * C_ * C_];
    __shared__ float sg[C_], sb[C_];
    const int tid = threadIdx.x;
    for (int i = tid; i < 2 * C_ * C_; i += 256) sW[i] = Wab[i];
    if (tid < C_) { sg[tid] = gamma[tid]; sb[tid] = beta[tid]; }
    __syncthreads();

    const int s = blockIdx.x;
    const int n = tid;
    const float* xp = m + ((size_t)s * NSEQ + n) * C_;

    float x[C_];
#pragma unroll
    for (int q = 0; q < C_ / 4; q++) {
        float4 v = reinterpret_cast<const float4*>(xp)[q];
        x[4*q+0] = v.x; x[4*q+1] = v.y; x[4*q+2] = v.z; x[4*q+3] = v.w;
    }
    float mu = 0.f;
#pragma unroll
    for (int c = 0; c < C_; c++) mu += x[c];
    mu *= (1.f / C_);
    float var = 0.f;
#pragma unroll
    for (int c = 0; c < C_; c++) { float d = x[c] - mu; var += d * d; }
    var *= (1.f / C_);
    const float rstd = rsqrtf(var + 1e-5f);
#pragma unroll
    for (int c = 0; c < C_; c++) x[c] = (x[c] - mu) * rstd * sg[c] + sb[c];

#pragma unroll 4
    for (int d = 0; d < C_; d++) {
        float acc = 0.f;
#pragma unroll
        for (int c = 0; c < C_; c++) acc += x[c] * sW[d * C_ + c];
        split_store(g_Ahi, g_Alo, (size_t)(s * C_ + d) * NSEQ + n, acc * (1.f / NSEQ));
    }
#pragma unroll 4
    for (int d = 0; d < C_; d++) {
        float acc = 0.f;
#pragma unroll
        for (int c = 0; c < C_; c++) acc += x[c] * sW[(C_ + d) * C_ + c];
        split_store(g_Bhi, g_Blo, (size_t)(s * C_ + d) * NSEQ + n, acc);
    }
}

__global__ __launch_bounds__(256) void wsplit_kernel(const float* __restrict__ W) {
    int i = blockIdx.x * 256 + threadIdx.x;
    split_store(g_Whi, g_Wlo, i, W[i]);
}

// ---------------------------------------------------------------------------
// Unified tensor-core GEMM: CTA tile 128x128, 4 warps of 64x64, 3-pass split.
// 3-stage cp.async pipeline (2-deep prefetch), ONE __syncthreads per stage.
// 2 CTAs/SM. MODE 0: A'*B'^T -> permuted hi/lo O. MODE 1: O*W^T + bias.
// ---------------------------------------------------------------------------
template <int KD, int MODE>
__global__ __launch_bounds__(128, 2) void gemm_kernel(
    const float* __restrict__ bout, float* __restrict__ out)
{
    extern __shared__ __align__(128) char smem[];
    const uint32_t sbase = smem_u32(smem);
    const int tid = threadIdx.x, lane = tid & 31, w = tid >> 5;
    const int wm = (w >> 1) * 64, wn = (w & 1) * 64;
    const int row0 = blockIdx.y * 128;
    const int col0 = blockIdx.x * 128;

    const bf16 *pAh, *pAl, *pBh, *pBl;
    if (MODE == 0) {
        pAh = g_Ahi + (size_t)row0 * KD;  pAl = g_Alo + (size_t)row0 * KD;
        pBh = g_Bhi + (size_t)col0 * KD;  pBl = g_Blo + (size_t)col0 * KD;
    } else {
        pAh = g_Ohi + (size_t)row0 * KD;  pAl = g_Olo + (size_t)row0 * KD;
        pBh = g_Whi;                      pBl = g_Wlo;
    }

    float bias[16];
    if (MODE == 1) {
#pragma unroll
        for (int nt = 0; nt < 8; nt++) {
            const int col = wn + nt * 8 + (lane & 3) * 2;
            bias[nt * 2]     = bout[col];
            bias[nt * 2 + 1] = bout[col + 1];
        }
    }

    float c[4][8][4];
#pragma unroll
    for (int a = 0; a < 4; a++)
#pragma unroll
        for (int b = 0; b < 8; b++)
#pragma unroll
            for (int d = 0; d < 4; d++) c[a][b][d] = 0.f;

    const int NS = KD / 32;

    // prologue: stages 0 and 1 in flight
    {
        stage_load<KD>(pAh, sbase,           0, tid);
        stage_load<KD>(pAl, sbase + OFF_ALO, 0, tid);
        stage_load<KD>(pBh, sbase + OFF_BHI, 0, tid);
        stage_load<KD>(pBl, sbase + OFF_BLO, 0, tid);
        cp_commit();
        const uint32_t b1 = sbase + STAGE_B;
        stage_load<KD>(pAh, b1,           32, tid);
        stage_load<KD>(pAl, b1 + OFF_ALO, 32, tid);
        stage_load<KD>(pBh, b1 + OFF_BHI, 32, tid);
        stage_load<KD>(pBl, b1 + OFF_BLO, 32, tid);
        cp_commit();
    }

    int rd = 0, wr = 2;   // stage indices mod 3
#pragma unroll 1
    for (int s = 0; s < NS; s++) {
        cp_wait<1>();          // stage s resident (s+1 may still fly)
        __syncthreads();       // all warps done reading the buffer we overwrite next
        if (s + 2 < NS) {
            const uint32_t nb = sbase + (uint32_t)wr * STAGE_B;
            const int k0 = (s + 2) * 32;
            stage_load<KD>(pAh, nb,           k0, tid);
            stage_load<KD>(pAl, nb + OFF_ALO, k0, tid);
            stage_load<KD>(pBh, nb + OFF_BHI, k0, tid);
            stage_load<KD>(pBl, nb + OFF_BLO, k0, tid);
        }
        cp_commit();           // one group per iteration (empty in tail)
        compute_stage(sbase + (uint32_t)rd * STAGE_B, wm, wn, lane, c);
        rd = (rd == 2) ? 0 : rd + 1;
        wr = (wr == 2) ? 0 : wr + 1;
    }

    const int R0 = row0 + wm + (lane >> 2);
    if (MODE == 0) {
#pragma unroll
        for (int mt = 0; mt < 4; mt++) {
#pragma unroll
            for (int h = 0; h < 2; h++) {
                const int R = R0 + mt * 16 + h * 8;
                const int i = R >> 5, cc = R & 31;
                const size_t rowbase = (size_t)i * (S_ * KOUT) + (size_t)cc * C_;
#pragma unroll
                for (int nt = 0; nt < 8; nt++) {
                    const int Cc = col0 + wn + nt * 8 + (lane & 3) * 2;
                    const int j = Cc >> 5, dd = Cc & 31;
                    const size_t idx = rowbase + (size_t)j * KOUT + dd;
                    float v0 = c[mt][nt][h * 2 + 0];
                    float v1 = c[mt][nt][h * 2 + 1];
                    bf16 h0 = __float2bfloat16_rn(v0), h1 = __float2bfloat16_rn(v1);
                    __nv_bfloat162 hp; hp.x = h0; hp.y = h1;
                    __nv_bfloat162 lp;
                    lp.x = __float2bfloat16_rn(v0 - __bfloat162float(h0));
                    lp.y = __float2bfloat16_rn(v1 - __bfloat162float(h1));
                    *reinterpret_cast<__nv_bfloat162*>(g_Ohi + idx) = hp;
                    *reinterpret_cast<__nv_bfloat162*>(g_Olo + idx) = lp;
                }
            }
        }
    } else {
#pragma unroll
        for (int mt = 0; mt < 4; mt++) {
#pragma unroll
            for (int h = 0; h < 2; h++) {
                const int R = R0 + mt * 16 + h * 8;
#pragma unroll
                for (int nt = 0; nt < 8; nt++) {
                    const int col = wn + nt * 8 + (lane & 3) * 2;
                    float2 v;
                    v.x = c[mt][nt][h * 2 + 0] + bias[nt * 2];
                    v.y = c[mt][nt][h * 2 + 1] + bias[nt * 2 + 1];
                    *reinterpret_cast<float2*>(out + (size_t)R * CZ + col) = v;
                }
            }
        }
    }
}

// ---------------------------------------------------------------------------
extern "C" void kernel_launch(void* const* d_in, const int* in_sizes, int n_in,
                              void* d_out, int out_size)
{
    const float* m_si = (const float*)d_in[0];
    const float* gam  = (const float*)d_in[1];
    const float* bet  = (const float*)d_in[2];
    const float* Wab  = (const float*)d_in[3];
    const float* Wout = (const float*)d_in[4];
    const float* bout = (const float*)d_in[5];
    float* out = (float*)d_out;

    cudaFuncSetAttribute(gemm_kernel<NSEQ, 0>,
                         cudaFuncAttributeMaxDynamicSharedMemorySize, SMEM_BYTES);
    cudaFuncSetAttribute(gemm_kernel<KOUT, 1>,
                         cudaFuncAttributeMaxDynamicSharedMemorySize, SMEM_BYTES);

    prep_kernel<<<S_, 256>>>(m_si, gam, bet, Wab);
    wsplit_kernel<<<512, 256>>>(Wout);
    gemm_kernel<NSEQ, 0><<<dim3(64, 64), 128, SMEM_BYTES>>>(nullptr, nullptr);
    gemm_kernel<KOUT, 1><<<dim3(1, 512), 128, SMEM_BYTES>>>(bout, out);
}

// round 11
// speedup vs baseline: 7.0223x; 2.3536x over previous
#include <cuda_runtime.h>
#include <cuda_fp16.h>
#include <cstdint>
#include <cstddef>

#define S_    256
#define NSEQ  256
#define C_    32
#define CZ    128
#define SC    8192      /* S*C */
#define KOUT  1024      /* C*C */

// ----- scratch (__device__ globals; allocation-free rule) -------------------
__device__ __align__(16) __half g_A[SC * NSEQ];               // 4 MB, K-major (unscaled)
__device__ __align__(16) __half g_B[SC * NSEQ];               // 4 MB
__device__ __align__(16) __half g_O[(size_t)S_ * S_ * KOUT];  // 134 MB
__device__ __align__(16) __half g_W[CZ * KOUT];               // 256 KB

#define DEVINL __device__ __forceinline__

// ----- PTX helpers (sm_80-era; required for plain sm_100 ptxas target) ------
DEVINL uint32_t smem_u32(const void* p) {
    uint32_t a;
    asm("{ .reg .u64 t; cvta.to.shared.u64 t, %1; cvt.u32.u64 %0, t; }"
        : "=r"(a) : "l"(p));
    return a;
}
DEVINL void cp16(uint32_t sdst, const void* gsrc) {
    asm volatile("cp.async.cg.shared.global [%0], [%1], 16;"
                 :: "r"(sdst), "l"(__cvta_generic_to_global(gsrc)) : "memory");
}
DEVINL void cp_commit() { asm volatile("cp.async.commit_group;" ::: "memory"); }
template <int N>
DEVINL void cp_wait() { asm volatile("cp.async.wait_group %0;" :: "n"(N) : "memory"); }

DEVINL void ldm4(uint32_t* r, uint32_t addr) {
    asm volatile("ldmatrix.sync.aligned.m8n8.x4.shared.b16 {%0,%1,%2,%3}, [%4];"
                 : "=r"(r[0]), "=r"(r[1]), "=r"(r[2]), "=r"(r[3]) : "r"(addr));
}
DEVINL void mma16816(float* c, const uint32_t* a, const uint32_t* b) {
    asm volatile(
        "mma.sync.aligned.m16n8k16.row.col.f32.f16.f16.f32 "
        "{%0,%1,%2,%3}, {%4,%5,%6,%7}, {%8,%9}, {%0,%1,%2,%3};"
        : "+f"(c[0]), "+f"(c[1]), "+f"(c[2]), "+f"(c[3])
        : "r"(a[0]), "r"(a[1]), "r"(a[2]), "r"(a[3]), "r"(b[0]), "r"(b[1]));
}

// XOR-swizzled smem tile: 128 rows x 64 B (32 fp16), no padding.
// chunk ch (16B) at row r -> column (ch ^ ((r>>1)&3)). Conflict-free ldmatrix
// (8 distinct 16B bank-groups per 8-row read) and balanced 16B stores.
DEVINL uint32_t swz(int r, int ch) {
    return (uint32_t)(r * 64 + ((ch ^ ((r >> 1) & 3)) << 4));
}

#define T_CB     8192              /* 128 rows * 64 B */
#define OFF_B    T_CB
#define STAGE_B  (2 * T_CB)        /* 16384: A tile + B tile */
#define NSTAGE   4
#define SMEM_BYTES (NSTAGE * STAGE_B)   /* 65536/CTA; 2 CTAs/SM = 128 KB */

// Load 128 rows x 32 fp16 into swizzled smem tile; 128 threads, 4 cp16 each.
template <int RS>
DEVINL void stage_load(const __half* __restrict__ g, uint32_t sdst, int k0, int tid) {
#pragma unroll
    for (int u = 0; u < 4; u++) {
        int q = u * 128 + tid;
        int r = q >> 2, ch = q & 3;
        cp16(sdst + swz(r, ch), g + (size_t)r * RS + k0 + ch * 8);
    }
}

// One BK=32 stage of single-pass fp16 MMAs; warp tile 64x64.
DEVINL void compute_stage(uint32_t st, int wm, int wn, int lane, float c[4][8][4]) {
    const int grp = lane >> 3, lr = lane & 7;
    const int arow = wm + lr + (grp & 1) * 8;
    const int brow = wn + lr + (grp >> 1) * 8;
#pragma unroll
    for (int kh = 0; kh < 2; kh++) {
        const int ag = kh * 2 + (grp >> 1);
        const int bg = kh * 2 + (grp & 1);
        uint32_t a[4][4];
#pragma unroll
        for (int mt = 0; mt < 4; mt++)
            ldm4(a[mt], st + swz(arow + mt * 16, ag));
#pragma unroll
        for (int bt = 0; bt < 4; bt++) {
            uint32_t b[4];
            ldm4(b, st + OFF_B + swz(brow + bt * 16, bg));
#pragma unroll
            for (int mt = 0; mt < 4; mt++) {
                mma16816(c[mt][bt * 2],     a[mt], b);
                mma16816(c[mt][bt * 2 + 1], a[mt], b + 2);
            }
        }
    }
}

// ---------------------------------------------------------------------------
// Kernel 1: LayerNorm + projection -> fp16 operands (unscaled; 1/N in epilogue)
// ---------------------------------------------------------------------------
__global__ __launch_bounds__(256) void prep_kernel(
    const float* __restrict__ m, const float* __restrict__ gamma,
    const float* __restrict__ beta, const float* __restrict__ Wab)
{
    __shared__ float sW[2 * C_ * C_];
    __shared__ float sg[C_], sb[C_];
    const int tid = threadIdx.x;
    for (int i = tid; i < 2 * C_ * C_; i += 256) sW[i] = Wab[i];
    if (tid < C_) { sg[tid] = gamma[tid]; sb[tid] = beta[tid]; }
    __syncthreads();

    const int s = blockIdx.x;
    const int n = tid;
    const float* xp = m + ((size_t)s * NSEQ + n) * C_;

    float x[C_];
#pragma unroll
    for (int q = 0; q < C_ / 4; q++) {
        float4 v = reinterpret_cast<const float4*>(xp)[q];
        x[4*q+0] = v.x; x[4*q+1] = v.y; x[4*q+2] = v.z; x[4*q+3] = v.w;
    }
    float mu = 0.f;
#pragma unroll
    for (int c = 0; c < C_; c++) mu += x[c];
    mu *= (1.f / C_);
    float var = 0.f;
#pragma unroll
    for (int c = 0; c < C_; c++) { float d = x[c] - mu; var += d * d; }
    var *= (1.f / C_);
    const float rstd = rsqrtf(var + 1e-5f);
#pragma unroll
    for (int c = 0; c < C_; c++) x[c] = (x[c] - mu) * rstd * sg[c] + sb[c];

#pragma unroll 4
    for (int d = 0; d < C_; d++) {
        float acc = 0.f;
#pragma unroll
        for (int c = 0; c < C_; c++) acc += x[c] * sW[d * C_ + c];
        g_A[(size_t)(s * C_ + d) * NSEQ + n] = __float2half_rn(acc);
    }
#pragma unroll 4
    for (int d = 0; d < C_; d++) {
        float acc = 0.f;
#pragma unroll
        for (int c = 0; c < C_; c++) acc += x[c] * sW[(C_ + d) * C_ + c];
        g_B[(size_t)(s * C_ + d) * NSEQ + n] = __float2half_rn(acc);
    }
}

__global__ __launch_bounds__(256) void wconv_kernel(const float* __restrict__ W) {
    int i = blockIdx.x * 256 + threadIdx.x;
    g_W[i] = __float2half_rn(W[i]);
}

// ---------------------------------------------------------------------------
// Unified tensor-core GEMM: CTA tile 128x128, 4 warps of 64x64, fp16 1-pass.
// 4-stage cp.async pipeline (3-deep prefetch), one __syncthreads per stage.
// 2 CTAs/SM. MODE 0: A*B^T (scaled 1/N) -> permuted fp16 O. MODE 1: O*W^T + b.
// ---------------------------------------------------------------------------
template <int KD, int MODE>
__global__ __launch_bounds__(128, 2) void gemm_kernel(
    const float* __restrict__ bout, float* __restrict__ out)
{
    extern __shared__ __align__(128) char smem[];
    const uint32_t sbase = smem_u32(smem);
    const int tid = threadIdx.x, lane = tid & 31, w = tid >> 5;
    const int wm = (w >> 1) * 64, wn = (w & 1) * 64;
    const int row0 = blockIdx.y * 128;
    const int col0 = blockIdx.x * 128;

    const __half *pA, *pB;
    if (MODE == 0) {
        pA = g_A + (size_t)row0 * KD;
        pB = g_B + (size_t)col0 * KD;
    } else {
        pA = g_O + (size_t)row0 * KD;
        pB = g_W;
    }

    float bias[16];
    if (MODE == 1) {
#pragma unroll
        for (int nt = 0; nt < 8; nt++) {
            const int col = wn + nt * 8 + (lane & 3) * 2;
            bias[nt * 2]     = bout[col];
            bias[nt * 2 + 1] = bout[col + 1];
        }
    }

    float c[4][8][4];
#pragma unroll
    for (int a = 0; a < 4; a++)
#pragma unroll
        for (int b = 0; b < 8; b++)
#pragma unroll
            for (int d = 0; d < 4; d++) c[a][b][d] = 0.f;

    const int NS = KD / 32;

    // prologue: stages 0..2 in flight
#pragma unroll
    for (int p = 0; p < 3; p++) {
        const uint32_t bp = sbase + (uint32_t)p * STAGE_B;
        stage_load<KD>(pA, bp,         p * 32, tid);
        stage_load<KD>(pB, bp + OFF_B, p * 32, tid);
        cp_commit();
    }

#pragma unroll 1
    for (int s = 0; s < NS; s++) {
        cp_wait<2>();          // stage s resident (s+1, s+2 may still fly)
        __syncthreads();       // all warps done reading the buffer we overwrite
        if (s + 3 < NS) {
            const uint32_t nb = sbase + (uint32_t)((s + 3) & 3) * STAGE_B;
            const int k0 = (s + 3) * 32;
            stage_load<KD>(pA, nb,         k0, tid);
            stage_load<KD>(pB, nb + OFF_B, k0, tid);
        }
        cp_commit();           // one group per iteration (empty in tail)
        compute_stage(sbase + (uint32_t)(s & 3) * STAGE_B, wm, wn, lane, c);
    }

    const int R0 = row0 + wm + (lane >> 2);
    if (MODE == 0) {
#pragma unroll
        for (int mt = 0; mt < 4; mt++) {
#pragma unroll
            for (int h = 0; h < 2; h++) {
                const int R = R0 + mt * 16 + h * 8;
                const int i = R >> 5, cc = R & 31;
                const size_t rowbase = (size_t)i * (S_ * KOUT) + (size_t)cc * C_;
#pragma unroll
                for (int nt = 0; nt < 8; nt++) {
                    const int Cc = col0 + wn + nt * 8 + (lane & 3) * 2;
                    const int j = Cc >> 5, dd = Cc & 31;
                    __half2 hv;
                    hv.x = __float2half_rn(c[mt][nt][h * 2 + 0] * (1.f / NSEQ));
                    hv.y = __float2half_rn(c[mt][nt][h * 2 + 1] * (1.f / NSEQ));
                    *reinterpret_cast<__half2*>(
                        g_O + rowbase + (size_t)j * KOUT + dd) = hv;
                }
            }
        }
    } else {
#pragma unroll
        for (int mt = 0; mt < 4; mt++) {
#pragma unroll
            for (int h = 0; h < 2; h++) {
                const int R = R0 + mt * 16 + h * 8;
#pragma unroll
                for (int nt = 0; nt < 8; nt++) {
                    const int col = wn + nt * 8 + (lane & 3) * 2;
                    float2 v;
                    v.x = c[mt][nt][h * 2 + 0] + bias[nt * 2];
                    v.y = c[mt][nt][h * 2 + 1] + bias[nt * 2 + 1];
                    *reinterpret_cast<float2*>(out + (size_t)R * CZ + col) = v;
                }
            }
        }
    }
}

// ---------------------------------------------------------------------------
extern "C" void kernel_launch(void* const* d_in, const int* in_sizes, int n_in,
                              void* d_out, int out_size)
{
    const float* m_si = (const float*)d_in[0];
    const float* gam  = (const float*)d_in[1];
    const float* bet  = (const float*)d_in[2];
    const float* Wab  = (const float*)d_in[3];
    const float* Wout = (const float*)d_in[4];
    const float* bout = (const float*)d_in[5];
    float* out = (float*)d_out;

    cudaFuncSetAttribute(gemm_kernel<NSEQ, 0>,
                         cudaFuncAttributeMaxDynamicSharedMemorySize, SMEM_BYTES);
    cudaFuncSetAttribute(gemm_kernel<KOUT, 1>,
                         cudaFuncAttributeMaxDynamicSharedMemorySize, SMEM_BYTES);

    prep_kernel<<<S_, 256>>>(m_si, gam, bet, Wab);
    wconv_kernel<<<512, 256>>>(Wout);
    gemm_kernel<NSEQ, 0><<<dim3(64, 64), 128, SMEM_BYTES>>>(nullptr, nullptr);
    gemm_kernel<KOUT, 1><<<dim3(1, 512), 128, SMEM_BYTES>>>(bout, out);
}